// round 3
// baseline (speedup 1.0000x reference)
#include <cuda_runtime.h>
#include <cstdint>
#include <cstddef>

#define IN_F   4096
#define OUT_F  11008
#define BATCH  32
#define N_TILE 128
#define K_TILE 64
#define STAGES 3
#define THREADS 128
#define NITER  (IN_F / K_TILE)

// Two-level residual quantization of x: plane 0 = q1 (x*16), plane 1 = q2 (residual*4096)
__device__ __align__(16) signed char g_xq[2 * BATCH * IN_F];
__device__ int g_w_is_i32;

__global__ void quantize_x_kernel(const float* __restrict__ x) {
    int i = blockIdx.x * blockDim.x + threadIdx.x;
    if (i >= BATCH * IN_F) return;
    float v  = x[i];
    float q1 = rintf(v * 16.0f);
    q1 = fminf(fmaxf(q1, -127.0f), 127.0f);
    float r  = v - q1 * 0.0625f;
    float q2 = rintf(r * 4096.0f);
    q2 = fminf(fmaxf(q2, -127.0f), 127.0f);
    g_xq[i]                 = (signed char)(int)q1;
    g_xq[BATCH * IN_F + i]  = (signed char)(int)q2;
}

// If W was marshalled as int32 (one int per weight), every word is in [-128,127].
// If it is raw int8 bytes, a random 4-byte word lands there with prob ~2^-24.
__global__ void detect_w_dtype(const int* __restrict__ w) {
    if (threadIdx.x == 0) {
        int ok = 1;
        #pragma unroll 4
        for (int i = 0; i < 256; ++i) {
            int v = w[i];
            if (v < -128 || v > 127) { ok = 0; break; }
        }
        g_w_is_i32 = ok;
    }
}

__device__ __forceinline__ void cp_async16(void* sdst, const void* gsrc) {
    uint32_t s = (uint32_t)__cvta_generic_to_shared(sdst);
    asm volatile("cp.async.cg.shared.global [%0], [%1], 16;" :: "r"(s), "l"(gsrc));
}

__device__ __forceinline__ void mma_s8(int d[4], const int a[4], const int b[2]) {
    asm volatile(
        "mma.sync.aligned.m16n8k32.row.col.s32.s8.s8.s32 "
        "{%0,%1,%2,%3}, {%4,%5,%6,%7}, {%8,%9}, {%0,%1,%2,%3};"
        : "+r"(d[0]), "+r"(d[1]), "+r"(d[2]), "+r"(d[3])
        : "r"(a[0]), "r"(a[1]), "r"(a[2]), "r"(a[3]), "r"(b[0]), "r"(b[1]));
}

// ===================== Path A: W stored as int8 bytes =====================
__global__ __launch_bounds__(THREADS, 1)
void qlinear_gemm_i8(const signed char* __restrict__ W,
                     const float* __restrict__ scale_p,
                     const float* __restrict__ bias,
                     float* __restrict__ out) {
    if (g_w_is_i32) return;

    __shared__ __align__(16) signed char Ws[STAGES][N_TILE][K_TILE + 16];
    __shared__ __align__(16) signed char Xs[STAGES][2 * BATCH][K_TILE + 16];

    const int tid  = threadIdx.x;
    const int n0   = blockIdx.x * N_TILE;
    const int lane = tid & 31;
    const int warp = tid >> 5;
    const int wm   = warp & 1;
    const int wn   = warp >> 1;
    const int g    = lane >> 2;
    const int q    = lane & 3;

    auto load_stage = [&](int s, int k0) {
        #pragma unroll
        for (int c = tid; c < (N_TILE * K_TILE) / 16; c += THREADS) {
            int row = c >> 2, cb = c & 3;
            cp_async16(&Ws[s][row][cb * 16],
                       W + (size_t)(n0 + row) * IN_F + k0 + cb * 16);
        }
        #pragma unroll
        for (int c = tid; c < (2 * BATCH * K_TILE) / 16; c += THREADS) {
            int row = c >> 2, cb = c & 3;
            cp_async16(&Xs[s][row][cb * 16],
                       g_xq + (size_t)row * IN_F + k0 + cb * 16);
        }
    };

    int acc1[8][4], acc2[8][4];
    #pragma unroll
    for (int f = 0; f < 8; ++f)
        #pragma unroll
        for (int r = 0; r < 4; ++r) { acc1[f][r] = 0; acc2[f][r] = 0; }

    for (int s = 0; s < STAGES - 1; ++s) {
        load_stage(s, s * K_TILE);
        asm volatile("cp.async.commit_group;");
    }

    const int arow_hi = wm * 16 + g;
    const int arow_lo = arow_hi + 32;

    for (int it = 0; it < NITER; ++it) {
        asm volatile("cp.async.wait_group %0;" :: "n"(STAGES - 2));
        __syncthreads();
        const int s = it % STAGES;

        #pragma unroll
        for (int ks = 0; ks < K_TILE / 32; ++ks) {
            const int kb = ks * 32 + q * 4;
            int a1[4], a2[4];
            a1[0] = *(const int*)&Xs[s][arow_hi    ][kb];
            a1[1] = *(const int*)&Xs[s][arow_hi + 8][kb];
            a1[2] = *(const int*)&Xs[s][arow_hi    ][kb + 16];
            a1[3] = *(const int*)&Xs[s][arow_hi + 8][kb + 16];
            a2[0] = *(const int*)&Xs[s][arow_lo    ][kb];
            a2[1] = *(const int*)&Xs[s][arow_lo + 8][kb];
            a2[2] = *(const int*)&Xs[s][arow_lo    ][kb + 16];
            a2[3] = *(const int*)&Xs[s][arow_lo + 8][kb + 16];
            #pragma unroll
            for (int f = 0; f < 8; ++f) {
                const int n = wn * 64 + f * 8 + g;
                int b[2];
                b[0] = *(const int*)&Ws[s][n][kb];
                b[1] = *(const int*)&Ws[s][n][kb + 16];
                mma_s8(acc1[f], a1, b);
                mma_s8(acc2[f], a2, b);
            }
        }

        const int pf = it + STAGES - 1;
        if (pf < NITER) load_stage(pf % STAGES, pf * K_TILE);
        asm volatile("cp.async.commit_group;");
    }

    const float sc = __ldg(scale_p);
    const float s1 = 0.0625f;
    const float s2 = 1.0f / 4096.0f;
    #pragma unroll
    for (int f = 0; f < 8; ++f) {
        const int n = n0 + wn * 64 + f * 8 + q * 2;
        const float2 bb = *(const float2*)&bias[n];
        const int r0 = wm * 16 + g;
        const int r1 = r0 + 8;
        float v0 = fmaf(sc, fmaf(s1, (float)acc1[f][0], s2 * (float)acc2[f][0]), bb.x);
        float v1 = fmaf(sc, fmaf(s1, (float)acc1[f][1], s2 * (float)acc2[f][1]), bb.y);
        float v2 = fmaf(sc, fmaf(s1, (float)acc1[f][2], s2 * (float)acc2[f][2]), bb.x);
        float v3 = fmaf(sc, fmaf(s1, (float)acc1[f][3], s2 * (float)acc2[f][3]), bb.y);
        *(float2*)&out[(size_t)r0 * OUT_F + n] = make_float2(v0, v1);
        *(float2*)&out[(size_t)r1 * OUT_F + n] = make_float2(v2, v3);
    }
}

// ===================== Path B: W stored as int32 words =====================
// Raw int32 tiles streamed to smem via cp.async; fragment load gathers low
// bytes with PRMT (low byte of an int32 in [-128,127] IS the int8 value).
#define WROW_BYTES 320                       // 256B data + 64B pad (conflict-free LDS.128)
#define WSTAGE_BYTES (N_TILE * WROW_BYTES)   // 40960
#define XROW_BYTES 80
#define XSTAGE_BYTES (2 * BATCH * XROW_BYTES)
#define DSM_TOTAL (STAGES * WSTAGE_BYTES + STAGES * XSTAGE_BYTES)

__global__ __launch_bounds__(THREADS, 1)
void qlinear_gemm_i32(const int* __restrict__ W32,
                      const float* __restrict__ scale_p,
                      const float* __restrict__ bias,
                      float* __restrict__ out) {
    if (!g_w_is_i32) return;

    extern __shared__ __align__(128) char dsm[];
    char* rawW = dsm;                                  // [STAGES][128][320]
    char* Xs   = dsm + STAGES * WSTAGE_BYTES;          // [STAGES][64][80]

    const int tid  = threadIdx.x;
    const int n0   = blockIdx.x * N_TILE;
    const int lane = tid & 31;
    const int warp = tid >> 5;       // warp owns n columns [warp*32, warp*32+32)
    const int g    = lane >> 2;      // 0..7
    const int q    = lane & 3;       // 0..3

    auto load_stage = [&](int s, int k0) {
        // W: 128 rows x 64 int32 = 2048 16B chunks; half-warp per 256B row.
        char* wbase = rawW + s * WSTAGE_BYTES;
        #pragma unroll
        for (int i = 0; i < 16; ++i) {
            int c = i * THREADS + tid;
            int row = c >> 4, part = c & 15;
            cp_async16(wbase + row * WROW_BYTES + part * 16,
                       W32 + (size_t)(n0 + row) * IN_F + k0 + part * 4);
        }
        char* xbase = Xs + s * XSTAGE_BYTES;
        #pragma unroll
        for (int i = 0; i < 2; ++i) {
            int c = i * THREADS + tid;
            int row = c >> 2, cb = c & 3;
            cp_async16(xbase + row * XROW_BYTES + cb * 16,
                       g_xq + (size_t)row * IN_F + k0 + cb * 16);
        }
    };

    int acc[4][4][4];   // [m_tile][n_frag][reg]; m 0..1 = q1 plane, 2..3 = q2 plane
    #pragma unroll
    for (int t = 0; t < 4; ++t)
        #pragma unroll
        for (int f = 0; f < 4; ++f)
            #pragma unroll
            for (int r = 0; r < 4; ++r) acc[t][f][r] = 0;

    for (int s = 0; s < STAGES - 1; ++s) {
        load_stage(s, s * K_TILE);
        asm volatile("cp.async.commit_group;");
    }

    for (int it = 0; it < NITER; ++it) {
        asm volatile("cp.async.wait_group %0;" :: "n"(STAGES - 2));
        __syncthreads();
        const int s = it % STAGES;
        const char* wst = rawW + s * WSTAGE_BYTES;
        const char* xst = Xs + s * XSTAGE_BYTES;

        #pragma unroll
        for (int ks = 0; ks < 2; ++ks) {
            const int kb = ks * 32 + q * 4;       // int8 k offset within tile
            int a[4][4];
            #pragma unroll
            for (int t = 0; t < 4; ++t) {
                const char* xr = xst + (t * 16 + g) * XROW_BYTES;
                a[t][0] = *(const int*)(xr + kb);
                a[t][1] = *(const int*)(xr + 8 * XROW_BYTES + kb);
                a[t][2] = *(const int*)(xr + kb + 16);
                a[t][3] = *(const int*)(xr + 8 * XROW_BYTES + kb + 16);
            }
            #pragma unroll
            for (int f = 0; f < 4; ++f) {
                const int n = warp * 32 + f * 8 + g;
                const char* wr = wst + n * WROW_BYTES + ks * 128 + q * 16;
                int4 w0 = *(const int4*)wr;          // int32s kb..kb+3
                int4 w1 = *(const int4*)(wr + 64);   // int32s kb+16..kb+19
                int b[2];
                b[0] = __byte_perm(__byte_perm(w0.x, w0.y, 0x0040),
                                   __byte_perm(w0.z, w0.w, 0x0040), 0x5410);
                b[1] = __byte_perm(__byte_perm(w1.x, w1.y, 0x0040),
                                   __byte_perm(w1.z, w1.w, 0x0040), 0x5410);
                #pragma unroll
                for (int t = 0; t < 4; ++t)
                    mma_s8(acc[t][f], a[t], b);
            }
        }

        const int pf = it + STAGES - 1;
        if (pf < NITER) load_stage(pf % STAGES, pf * K_TILE);
        asm volatile("cp.async.commit_group;");
    }

    const float sc = __ldg(scale_p);
    const float s1 = 0.0625f;
    const float s2 = 1.0f / 4096.0f;
    #pragma unroll
    for (int t = 0; t < 2; ++t) {          // output row tiles (q1 plane); t+2 = q2 plane
        #pragma unroll
        for (int f = 0; f < 4; ++f) {
            const int n = n0 + warp * 32 + f * 8 + q * 2;
            const float2 bb = *(const float2*)&bias[n];
            const int r0 = t * 16 + g;
            const int r1 = r0 + 8;
            float v0 = fmaf(sc, fmaf(s1, (float)acc[t][f][0], s2 * (float)acc[t + 2][f][0]), bb.x);
            float v1 = fmaf(sc, fmaf(s1, (float)acc[t][f][1], s2 * (float)acc[t + 2][f][1]), bb.y);
            float v2 = fmaf(sc, fmaf(s1, (float)acc[t][f][2], s2 * (float)acc[t + 2][f][2]), bb.x);
            float v3 = fmaf(sc, fmaf(s1, (float)acc[t][f][3], s2 * (float)acc[t + 2][f][3]), bb.y);
            *(float2*)&out[(size_t)r0 * OUT_F + n] = make_float2(v0, v1);
            *(float2*)&out[(size_t)r1 * OUT_F + n] = make_float2(v2, v3);
        }
    }
}

extern "C" void kernel_launch(void* const* d_in, const int* in_sizes, int n_in,
                              void* d_out, int out_size) {
    // Bind inputs by element count (ordering-proof): all four counts are distinct.
    const float* x = nullptr; const void* w = nullptr;
    const float* scale = nullptr; const float* bias = nullptr;
    for (int i = 0; i < n_in; ++i) {
        switch (in_sizes[i]) {
            case BATCH * IN_F:    x     = (const float*)d_in[i]; break;
            case OUT_F * IN_F:    w     = d_in[i];               break;
            case 1:               scale = (const float*)d_in[i]; break;
            case OUT_F:           bias  = (const float*)d_in[i]; break;
        }
    }
    float* out = (float*)d_out;

    static bool attr_done = false;
    if (!attr_done) {
        cudaFuncSetAttribute(qlinear_gemm_i32,
                             cudaFuncAttributeMaxDynamicSharedMemorySize, DSM_TOTAL);
        attr_done = true;
    }

    quantize_x_kernel<<<(BATCH * IN_F + 255) / 256, 256>>>(x);
    detect_w_dtype<<<1, 32>>>((const int*)w);
    qlinear_gemm_i8<<<OUT_F / N_TILE, THREADS>>>((const signed char*)w, scale, bias, out);
    qlinear_gemm_i32<<<OUT_F / N_TILE, THREADS, DSM_TOTAL>>>((const int*)w, scale, bias, out);
}

// round 5
// speedup vs baseline: 1.2413x; 1.2413x over previous
#include <cuda_runtime.h>
#include <cstdint>
#include <cstddef>

#define IN_F   4096
#define OUT_F  11008
#define BATCH  32
#define N_TILE 64
#define K_TILE 64
#define STAGES 4
#define THREADS 256
#define NITER  (IN_F / K_TILE)

#define WROW_BYTES 320                        // 256B data + 64B pad: conflict-free LDS.128
#define WSTAGE     (N_TILE * WROW_BYTES)      // 20480
#define XROW_BYTES 80                         // 64B data + 16B pad: conflict-free LDS.32
#define XSTAGE     (2 * BATCH * XROW_BYTES)   // 5120
#define STAGE_BYTES (WSTAGE + XSTAGE)         // 25600
#define DSM_TOTAL  (STAGES * STAGE_BYTES)     // 102400

// Two-level residual quantization of x: plane 0 = q1 (x*16), plane 1 = q2 (residual*4096)
__device__ __align__(16) signed char g_xq[2 * BATCH * IN_F];

__global__ void quantize_x_kernel(const float* __restrict__ x) {
    int i = blockIdx.x * blockDim.x + threadIdx.x;
    if (i >= BATCH * IN_F) return;
    float v  = x[i];
    float q1 = rintf(v * 16.0f);
    q1 = fminf(fmaxf(q1, -127.0f), 127.0f);
    float r  = v - q1 * 0.0625f;
    float q2 = rintf(r * 4096.0f);
    q2 = fminf(fmaxf(q2, -127.0f), 127.0f);
    g_xq[i]                 = (signed char)(int)q1;
    g_xq[BATCH * IN_F + i]  = (signed char)(int)q2;
}

__device__ __forceinline__ void cp_async16(void* sdst, const void* gsrc) {
    uint32_t s = (uint32_t)__cvta_generic_to_shared(sdst);
    asm volatile("cp.async.cg.shared.global [%0], [%1], 16;" :: "r"(s), "l"(gsrc));
}

__device__ __forceinline__ void mma_s8(int d[4], const int a[4], const int b[2]) {
    asm volatile(
        "mma.sync.aligned.m16n8k32.row.col.s32.s8.s8.s32 "
        "{%0,%1,%2,%3}, {%4,%5,%6,%7}, {%8,%9}, {%0,%1,%2,%3};"
        : "+r"(d[0]), "+r"(d[1]), "+r"(d[2]), "+r"(d[3])
        : "r"(a[0]), "r"(a[1]), "r"(a[2]), "r"(a[3]), "r"(b[0]), "r"(b[1]));
}

// W arrives as int32 words (one weight per word, value in [-128,127]); the low
// byte of each word IS the int8 value, gathered with PRMT from smem.
__global__ __launch_bounds__(THREADS, 2)
void qlinear_gemm_i32(const int* __restrict__ W32,
                      const float* __restrict__ scale_p,
                      const float* __restrict__ bias,
                      float* __restrict__ out) {
    extern __shared__ __align__(128) char dsm[];

    const int tid  = threadIdx.x;
    const int n0   = blockIdx.x * N_TILE;
    const int lane = tid & 31;
    const int warp = tid >> 5;       // 8 warps; warp owns n-cols [warp*8, warp*8+8)
    const int g    = lane >> 2;      // 0..7
    const int q    = lane & 3;       // 0..3

    auto load_stage = [&](int s, int k0) {
        char* wbase = dsm + s * STAGE_BYTES;
        char* xbase = wbase + WSTAGE;
        // W: 64 rows x 64 int32 = 1024 16B chunks; 4 per thread.
        #pragma unroll
        for (int i = 0; i < 4; ++i) {
            int c = i * THREADS + tid;
            int row = c >> 4, part = c & 15;
            cp_async16(wbase + row * WROW_BYTES + part * 16,
                       W32 + (size_t)(n0 + row) * IN_F + k0 + part * 4);
        }
        // X: 64 rows x 4 chunks = 256 chunks; 1 per thread.
        {
            int row = tid >> 2, cb = tid & 3;
            cp_async16(xbase + row * XROW_BYTES + cb * 16,
                       g_xq + (size_t)row * IN_F + k0 + cb * 16);
        }
    };

    int acc[4][4];   // [m_tile][reg]; t 0..1 = q1 plane (rows 0..31), 2..3 = q2 plane
    #pragma unroll
    for (int t = 0; t < 4; ++t)
        #pragma unroll
        for (int r = 0; r < 4; ++r) acc[t][r] = 0;

    #pragma unroll
    for (int s = 0; s < STAGES - 1; ++s) {
        load_stage(s, s * K_TILE);
        asm volatile("cp.async.commit_group;");
    }

    const int nloc = warp * 8 + g;

    for (int it = 0; it < NITER; ++it) {
        asm volatile("cp.async.wait_group %0;" :: "n"(STAGES - 2));
        __syncthreads();
        const int s = it & (STAGES - 1);
        const char* wst = dsm + s * STAGE_BYTES;
        const char* xst = wst + WSTAGE;

        #pragma unroll
        for (int ks = 0; ks < 2; ++ks) {
            const int kb = ks * 32 + q * 4;
            int a[4][4];
            #pragma unroll
            for (int t = 0; t < 4; ++t) {
                const char* xr = xst + (t * 16 + g) * XROW_BYTES;
                a[t][0] = *(const int*)(xr + kb);
                a[t][1] = *(const int*)(xr + 8 * XROW_BYTES + kb);
                a[t][2] = *(const int*)(xr + kb + 16);
                a[t][3] = *(const int*)(xr + 8 * XROW_BYTES + kb + 16);
            }
            const char* wr = wst + nloc * WROW_BYTES + ks * 128 + q * 16;
            int4 w0 = *(const int4*)wr;          // int32 words k..k+3
            int4 w1 = *(const int4*)(wr + 64);   // int32 words k+16..k+19
            int b[2];
            b[0] = __byte_perm(__byte_perm(w0.x, w0.y, 0x0040),
                               __byte_perm(w0.z, w0.w, 0x0040), 0x5410);
            b[1] = __byte_perm(__byte_perm(w1.x, w1.y, 0x0040),
                               __byte_perm(w1.z, w1.w, 0x0040), 0x5410);
            #pragma unroll
            for (int t = 0; t < 4; ++t)
                mma_s8(acc[t], a[t], b);
        }

        const int pf = it + STAGES - 1;
        if (pf < NITER) load_stage(pf & (STAGES - 1), pf * K_TILE);
        asm volatile("cp.async.commit_group;");
    }

    // Epilogue: out = scale * (acc_hi/16 + acc_lo/4096) + bias
    const float sc = __ldg(scale_p);
    const float s1 = 0.0625f;
    const float s2 = 1.0f / 4096.0f;
    #pragma unroll
    for (int t = 0; t < 2; ++t) {
        const int n = n0 + warp * 8 + q * 2;
        const float2 bb = *(const float2*)&bias[n];
        const int r0 = t * 16 + g;
        const int r1 = r0 + 8;
        float v0 = fmaf(sc, fmaf(s1, (float)acc[t][0], s2 * (float)acc[t + 2][0]), bb.x);
        float v1 = fmaf(sc, fmaf(s1, (float)acc[t][1], s2 * (float)acc[t + 2][1]), bb.y);
        float v2 = fmaf(sc, fmaf(s1, (float)acc[t][2], s2 * (float)acc[t + 2][2]), bb.x);
        float v3 = fmaf(sc, fmaf(s1, (float)acc[t][3], s2 * (float)acc[t + 2][3]), bb.y);
        *(float2*)&out[(size_t)r0 * OUT_F + n] = make_float2(v0, v1);
        *(float2*)&out[(size_t)r1 * OUT_F + n] = make_float2(v2, v3);
    }
}

extern "C" void kernel_launch(void* const* d_in, const int* in_sizes, int n_in,
                              void* d_out, int out_size) {
    // Bind inputs by element count (ordering-proof): all four counts are distinct.
    const float* x = nullptr; const void* w = nullptr;
    const float* scale = nullptr; const float* bias = nullptr;
    for (int i = 0; i < n_in; ++i) {
        switch (in_sizes[i]) {
            case BATCH * IN_F:    x     = (const float*)d_in[i]; break;
            case OUT_F * IN_F:    w     = d_in[i];               break;
            case 1:               scale = (const float*)d_in[i]; break;
            case OUT_F:           bias  = (const float*)d_in[i]; break;
        }
    }
    float* out = (float*)d_out;

    static bool attr_done = false;
    if (!attr_done) {
        cudaFuncSetAttribute(qlinear_gemm_i32,
                             cudaFuncAttributeMaxDynamicSharedMemorySize, DSM_TOTAL);
        attr_done = true;
    }

    quantize_x_kernel<<<(BATCH * IN_F + 255) / 256, 256>>>(x);
    qlinear_gemm_i32<<<OUT_F / N_TILE, THREADS, DSM_TOTAL>>>((const int*)w, scale, bias, out);
}